// round 8
// baseline (speedup 1.0000x reference)
#include <cuda_runtime.h>
#include <math.h>
#include <stdint.h>

// ---------------- problem constants ----------------
#define BB   128
#define DD   512
#define SS   30
#define HW   196
#define TT   12
#define NH   13
#define BDSZ (BB*DD)
#define U2D  (BB*2*DD)

// ---------------- device scratch ----------------
__device__ float g_KBp[(size_t)BB*HW*DD];
__device__ float g_chist[(size_t)NH*BDSZ];
__device__ float g_mhist[(size_t)NH*BDSZ];
__device__ float g_qi[BDSZ];
__device__ float g_cq0[BDSZ];
__device__ float g_v[BDSZ];
__device__ float g_mnew[BDSZ];
__device__ float g_msa[BDSZ];
__device__ float g_Wcomb[(size_t)3*DD*DD];
__device__ float g_bcomb[DD];
__device__ float g_p_cq[(size_t)4*BDSZ];
__device__ float g_p_mp[(size_t)4*BDSZ];
__device__ float g_p_U [(size_t)4*U2D];
__device__ float g_p_g [(size_t)4*BDSZ];
__device__ float g_p_z [(size_t)4*BDSZ];
__device__ float g_p_f [(size_t)12*BDSZ];
__device__ float g_p_set[(size_t)4*1024*DD];

// smem: As[32][132] tf32 + Ws[32][36] tf32 (uint32 units)
#define APITCH 132
#define WPITCH 36
#define SMSZ (32*APITCH + 32*WPITCH)

__device__ __forceinline__ uint32_t f2tf(float x)
{
    uint32_t r;
    asm("cvt.rna.tf32.f32 %0, %1;" : "=r"(r) : "f"(x));
    return r;
}

__device__ __forceinline__ void mma_tf32(float c[4],
    uint32_t a0, uint32_t a1, uint32_t a2, uint32_t a3,
    uint32_t b0, uint32_t b1)
{
    asm volatile(
        "mma.sync.aligned.m16n8k8.row.col.f32.tf32.tf32.f32 "
        "{%0,%1,%2,%3}, {%4,%5,%6,%7}, {%8,%9}, {%0,%1,%2,%3};"
        : "+f"(c[0]), "+f"(c[1]), "+f"(c[2]), "+f"(c[3])
        : "r"(a0), "r"(a1), "r"(a2), "r"(a3), "r"(b0), "r"(b1));
}

// ---------------- tf32 MMA 128x32 GEMM tile over KC k-range ----------------
// A pre-offset to k-base. wtrans=0: W (K,N) row-major pre-offset kbase*ldw;
// wtrans=1: W (N,K) row-major pre-offset kbase.
__device__ __noinline__ void gtile_mma(
    const float* __restrict__ A, int lda, int m0,
    const float* __restrict__ W, int ldw, int wtrans,
    int n0, int KC,
    float* __restrict__ out, int ldo, const float* __restrict__ bias,
    uint32_t* sm)
{
    uint32_t (*As)[APITCH] = (uint32_t(*)[APITCH])sm;
    uint32_t (*Ws)[WPITCH] = (uint32_t(*)[WPITCH])(sm + 32*APITCH);
    int tid = threadIdx.x, lane = tid & 31, warp = tid >> 5;
    int g = lane >> 2, t = lane & 3;
    int m0w = warp * 16;
    int lm = tid & 127, kq = (tid >> 7) * 16;    // A loader: 128 rows x 2 k-halves

    float c[4][4];
#pragma unroll
    for (int f = 0; f < 4; f++)
#pragma unroll
        for (int i = 0; i < 4; i++) c[f][i] = 0.f;

    for (int kt = 0; kt < KC; kt += 32) {
        // ---- load A (4 float4 per thread) ----
        const float* ap = A + (size_t)(m0 + lm) * lda + kt + kq;
        float4 av0 = *(const float4*)(ap);
        float4 av1 = *(const float4*)(ap + 4);
        float4 av2 = *(const float4*)(ap + 8);
        float4 av3 = *(const float4*)(ap + 12);
        // ---- load W (1 float4 per thread) ----
        float4 wv;
        int wkk, wn;
        if (wtrans) {
            wn = tid >> 3; wkk = (tid & 7) * 4;
            wv = *(const float4*)(W + (size_t)(n0 + wn) * ldw + kt + wkk);
        } else {
            wkk = tid >> 3; wn = (tid & 7) * 4;
            wv = *(const float4*)(W + (size_t)(kt + wkk) * ldw + n0 + wn);
        }
        __syncthreads();
        // ---- stage (with tf32 convert) ----
        As[kq + 0][lm] = f2tf(av0.x); As[kq + 1][lm] = f2tf(av0.y);
        As[kq + 2][lm] = f2tf(av0.z); As[kq + 3][lm] = f2tf(av0.w);
        As[kq + 4][lm] = f2tf(av1.x); As[kq + 5][lm] = f2tf(av1.y);
        As[kq + 6][lm] = f2tf(av1.z); As[kq + 7][lm] = f2tf(av1.w);
        As[kq + 8][lm] = f2tf(av2.x); As[kq + 9][lm] = f2tf(av2.y);
        As[kq +10][lm] = f2tf(av2.z); As[kq +11][lm] = f2tf(av2.w);
        As[kq +12][lm] = f2tf(av3.x); As[kq +13][lm] = f2tf(av3.y);
        As[kq +14][lm] = f2tf(av3.z); As[kq +15][lm] = f2tf(av3.w);
        if (wtrans) {
            Ws[wkk + 0][wn] = f2tf(wv.x); Ws[wkk + 1][wn] = f2tf(wv.y);
            Ws[wkk + 2][wn] = f2tf(wv.z); Ws[wkk + 3][wn] = f2tf(wv.w);
        } else {
            Ws[wkk][wn + 0] = f2tf(wv.x); Ws[wkk][wn + 1] = f2tf(wv.y);
            Ws[wkk][wn + 2] = f2tf(wv.z); Ws[wkk][wn + 3] = f2tf(wv.w);
        }
        __syncthreads();
        // ---- 4 k8 mma steps ----
#pragma unroll
        for (int ks = 0; ks < 4; ks++) {
            int k8 = ks * 8;
            uint32_t a0 = As[k8 + t    ][m0w + g];
            uint32_t a1 = As[k8 + t    ][m0w + g + 8];
            uint32_t a2 = As[k8 + t + 4][m0w + g];
            uint32_t a3 = As[k8 + t + 4][m0w + g + 8];
#pragma unroll
            for (int f = 0; f < 4; f++) {
                uint32_t b0 = Ws[k8 + t    ][f * 8 + g];
                uint32_t b1 = Ws[k8 + t + 4][f * 8 + g];
                mma_tf32(c[f], a0, a1, a2, a3, b0, b1);
            }
        }
    }

    // ---- epilogue ----
    int r0 = m0 + m0w + g;
#pragma unroll
    for (int f = 0; f < 4; f++) {
        int col = n0 + f * 8 + 2 * t;
        float2 lo = make_float2(c[f][0], c[f][1]);
        float2 hi = make_float2(c[f][2], c[f][3]);
        if (bias) {
            lo.x += bias[col]; lo.y += bias[col + 1];
            hi.x += bias[col]; hi.y += bias[col + 1];
        }
        *(float2*)(out + (size_t)r0 * ldo + col) = lo;
        *(float2*)(out + (size_t)(r0 + 8) * ldo + col) = hi;
    }
}

// ---------------- z-variant: A computed on the fly, y = (Σ4 pU)·(Σ4 pmp + bm) ----------------
__device__ __noinline__ void gtileZ_mma(
    const float* __restrict__ Wkb, int n0, int kbz,
    float* __restrict__ outp, const float* __restrict__ bm, uint32_t* sm)
{
    uint32_t (*As)[APITCH] = (uint32_t(*)[APITCH])sm;
    uint32_t (*Ws)[WPITCH] = (uint32_t(*)[WPITCH])(sm + 32*APITCH);
    int tid = threadIdx.x, lane = tid & 31, warp = tid >> 5;
    int g = lane >> 2, t = lane & 3;
    int m0w = warp * 16;
    int lm = tid & 127, kq = (tid >> 7) * 16;

    float c[4][4];
#pragma unroll
    for (int f = 0; f < 4; f++)
#pragma unroll
        for (int i = 0; i < 4; i++) c[f][i] = 0.f;

    for (int kt = 0; kt < 128; kt += 32) {
        float4 yv[4];
#pragma unroll
        for (int j = 0; j < 4; j++) {
            int k = kbz + kt + kq + 4 * j;
            size_t q2 = (size_t)lm * (2 * DD) + k;
            size_t q1 = (size_t)lm * DD + k;
            float4 u0 = *(const float4*)(g_p_U + q2);
            float4 u1 = *(const float4*)(g_p_U + (size_t)U2D + q2);
            float4 u2 = *(const float4*)(g_p_U + (size_t)2 * U2D + q2);
            float4 u3 = *(const float4*)(g_p_U + (size_t)3 * U2D + q2);
            float4 m0v = *(const float4*)(g_p_mp + q1);
            float4 m1v = *(const float4*)(g_p_mp + (size_t)BDSZ + q1);
            float4 m2v = *(const float4*)(g_p_mp + (size_t)2 * BDSZ + q1);
            float4 m3v = *(const float4*)(g_p_mp + (size_t)3 * BDSZ + q1);
            float4 bv  = *(const float4*)(bm + k);
            yv[j].x = (u0.x+u1.x+u2.x+u3.x) * (m0v.x+m1v.x+m2v.x+m3v.x+bv.x);
            yv[j].y = (u0.y+u1.y+u2.y+u3.y) * (m0v.y+m1v.y+m2v.y+m3v.y+bv.y);
            yv[j].z = (u0.z+u1.z+u2.z+u3.z) * (m0v.z+m1v.z+m2v.z+m3v.z+bv.z);
            yv[j].w = (u0.w+u1.w+u2.w+u3.w) * (m0v.w+m1v.w+m2v.w+m3v.w+bv.w);
        }
        int wn = tid >> 3, wkk = (tid & 7) * 4;
        float4 wv = *(const float4*)(Wkb + (size_t)(n0 + wn) * DD + kbz + kt + wkk);
        __syncthreads();
#pragma unroll
        for (int j = 0; j < 4; j++) {
            As[kq + 4*j + 0][lm] = f2tf(yv[j].x);
            As[kq + 4*j + 1][lm] = f2tf(yv[j].y);
            As[kq + 4*j + 2][lm] = f2tf(yv[j].z);
            As[kq + 4*j + 3][lm] = f2tf(yv[j].w);
        }
        Ws[wkk + 0][wn] = f2tf(wv.x); Ws[wkk + 1][wn] = f2tf(wv.y);
        Ws[wkk + 2][wn] = f2tf(wv.z); Ws[wkk + 3][wn] = f2tf(wv.w);
        __syncthreads();
#pragma unroll
        for (int ks = 0; ks < 4; ks++) {
            int k8 = ks * 8;
            uint32_t a0 = As[k8 + t    ][m0w + g];
            uint32_t a1 = As[k8 + t    ][m0w + g + 8];
            uint32_t a2 = As[k8 + t + 4][m0w + g];
            uint32_t a3 = As[k8 + t + 4][m0w + g + 8];
#pragma unroll
            for (int f = 0; f < 4; f++) {
                uint32_t b0 = Ws[k8 + t    ][f * 8 + g];
                uint32_t b1 = Ws[k8 + t + 4][f * 8 + g];
                mma_tf32(c[f], a0, a1, a2, a3, b0, b1);
            }
        }
    }
    int r0 = m0w + g;
#pragma unroll
    for (int f = 0; f < 4; f++) {
        int col = n0 + f * 8 + 2 * t;
        *(float2*)(outp + (size_t)r0 * DD + col) = make_float2(c[f][0], c[f][1]);
        *(float2*)(outp + (size_t)(r0 + 8) * DD + col) = make_float2(c[f][2], c[f][3]);
    }
}

// ---------------- setup: generic split-K partial GEMM ----------------
struct GP {
    const float* A; int lda; int K;
    const float* W; int wtrans; int ldw;
    float* part; int M; int N; int KC;
};
__global__ void __launch_bounds__(256) gpartial_k(const GP P)
{
    __shared__ uint32_t sm[SMSZ];
    int ntiles = P.N >> 5;
    int nt = blockIdx.x % ntiles;
    int mt = blockIdx.x / ntiles;
    int kb = blockIdx.y * P.KC;
    gtile_mma(P.A + kb, P.lda, mt * 128,
              P.wtrans ? (P.W + kb) : (P.W + (size_t)kb * P.ldw), P.ldw, P.wtrans,
              nt * 32, P.KC,
              P.part + (size_t)blockIdx.y * P.M * P.N, P.N, nullptr, sm);
}
__global__ void reduce0_k(const float* __restrict__ part, int nch, int MN, int N,
                          const float* __restrict__ bias, float* __restrict__ out)
{
    int idx = blockIdx.x * 256 + threadIdx.x;
    if (idx >= MN) return;
    float s = 0.f;
    for (int c = 0; c < nch; c++) s += part[(size_t)c * MN + idx];
    if (bias) s += bias[idx % N];
    out[idx] = s;
}

// ---------------- transpose KB (B,D,HW) -> KBp (B,HW,D) ----------------
__global__ void transpose_kb_k(const float* __restrict__ KB, float* __restrict__ KBp)
{
    __shared__ float tile[32][33];
    int b = blockIdx.z;
    int hw0 = blockIdx.x * 32, d0 = blockIdx.y * 32;
    int tx = threadIdx.x, ty = threadIdx.y;
    const float* src = KB + (size_t)b * DD * HW;
#pragma unroll
    for (int j = 0; j < 4; j++) {
        int d = d0 + ty + j * 8;
        int hw = hw0 + tx;
        if (hw < HW) tile[ty + j * 8][tx] = src[(size_t)d * HW + hw];
    }
    __syncthreads();
    float* dst = KBp + (size_t)b * HW * DD;
#pragma unroll
    for (int j = 0; j < 4; j++) {
        int hw = hw0 + ty + j * 8;
        if (hw < HW) dst[(size_t)hw * DD + d0 + tx] = tile[tx][ty + j * 8];
    }
}

// ---------------- bcomb = bwm @ Wam_bot + bam ----------------
__global__ void bcomb_k(const float* __restrict__ Wam, const float* __restrict__ bwm,
                        const float* __restrict__ bam)
{
    int n = blockIdx.x * 128 + threadIdx.x;
    float s = bam[n];
#pragma unroll 8
    for (int j = 0; j < DD; j++) s += bwm[j] * Wam[(size_t)(DD + j) * DD + n];
    g_bcomb[n] = s;
}

// ---------------- merged control + self attention (per-batch block) ----------------
__global__ void __launch_bounds__(128)
attn1_k(const float* __restrict__ cws, const float* __restrict__ wca,
        const float* __restrict__ wra, const float* __restrict__ wwa, int t)
{
    int b = blockIdx.x, tid = threadIdx.x;
    int lane = tid & 31, warp = tid >> 5;

    float accs[SS];
#pragma unroll
    for (int s = 0; s < SS; s++) accs[s] = 0.f;
#pragma unroll
    for (int i = 0; i < 4; i++) {
        int d = tid + i * 128;
        size_t j = (size_t)b * DD + d;
        float cqv = g_p_cq[j] + g_p_cq[BDSZ + j] + g_p_cq[2*BDSZ + j]
                  + g_p_cq[3*BDSZ + j] + g_cq0[j];
        float a = cqv * wca[d];
        const float* row = cws + j * SS;
#pragma unroll
        for (int s = 0; s < SS; s++) accs[s] += a * row[s];
    }
    __shared__ float wred[4][SS];
#pragma unroll
    for (int s = 0; s < SS; s++) {
        float x = accs[s];
        for (int off = 16; off; off >>= 1) x += __shfl_down_sync(~0u, x, off);
        if (lane == 0) wred[warp][s] = x;
    }
    __syncthreads();
    __shared__ float cattn[SS];
    if (warp == 0) {
        float val = (lane < SS) ? (wred[0][lane] + wred[1][lane] + wred[2][lane] + wred[3][lane]) : -1e30f;
        float mx = val;
        for (int off = 16; off; off >>= 1) mx = fmaxf(mx, __shfl_xor_sync(~0u, mx, off));
        float e = (lane < SS) ? expf(val - mx) : 0.f;
        float tot = e;
        for (int off = 16; off; off >>= 1) tot += __shfl_xor_sync(~0u, tot, off);
        if (lane < SS) cattn[lane] = e / tot;
    }
    __syncthreads();

    float ci[4];
#pragma unroll
    for (int i = 0; i < 4; i++) {
        int d = tid + i * 128;
        const float* row = cws + ((size_t)b * DD + d) * SS;
        float c = 0.f;
#pragma unroll
        for (int s = 0; s < SS; s++) c += cattn[s] * row[s];
        ci[i] = c;
        g_chist[(size_t)(t + 1) * BDSZ + (size_t)b * DD + d] = c;
        g_v[(size_t)b * DD + d] = c * wra[d];
    }

    float aw[4];
#pragma unroll
    for (int i = 0; i < 4; i++) aw[i] = ci[i] * wwa[tid + i * 128];
    float acct[TT];
#pragma unroll
    for (int tp = 0; tp < TT; tp++) acct[tp] = 0.f;
    for (int tp = 0; tp <= t; tp++) {
        const float* ch = g_chist + (size_t)tp * BDSZ + (size_t)b * DD;
        acct[tp] = aw[0] * ch[tid] + aw[1] * ch[tid + 128]
                 + aw[2] * ch[tid + 256] + aw[3] * ch[tid + 384];
    }
    __shared__ float wred2[4][TT];
#pragma unroll
    for (int tp = 0; tp < TT; tp++) {
        float x = acct[tp];
        for (int off = 16; off; off >>= 1) x += __shfl_down_sync(~0u, x, off);
        if (lane == 0) wred2[warp][tp] = x;
    }
    __syncthreads();
    __shared__ float sattn[TT];
    if (tid == 0) {
        int ntv = t + 1;
        float sl[TT];
        float mx = -1e30f;
        for (int tp = 0; tp < ntv; tp++) {
            float vv = wred2[0][tp] + wred2[1][tp] + wred2[2][tp] + wred2[3][tp];
            sl[tp] = vv;
            mx = fmaxf(mx, vv);
        }
        float tot = 0.f;
        for (int tp = 0; tp < ntv; tp++) { float e = expf(sl[tp] - mx); sl[tp] = e; tot += e; }
        for (int tp = 0; tp < ntv; tp++) sattn[tp] = sl[tp] / tot;
        for (int tp = ntv; tp < TT; tp++) sattn[tp] = 0.f;
    }
    __syncthreads();
#pragma unroll
    for (int i = 0; i < 4; i++) {
        int d = tid + i * 128;
        float sv = 0.f;
        for (int tp = 0; tp <= t; tp++)
            sv += sattn[tp] * g_mhist[(size_t)tp * BDSZ + (size_t)b * DD + d];
        g_msa[(size_t)b * DD + d] = sv;
    }
}

// ---------------- kB: U partials + cq_{t+1} partials + mp partials (256 blocks) ----------------
__global__ void __launch_bounds__(256)
kB_k(const float* ci, const float* mprev,
     const float* __restrict__ Wrm, const float* __restrict__ Wct,
     const float* __restrict__ Wm)
{
    __shared__ uint32_t sm[SMSZ];
    int blk = blockIdx.x;
    if (blk < 128) {
        int nt = blk & 31, ch = blk >> 5, kb = ch * 128;
        gtile_mma(g_v + kb, DD, 0, Wrm + kb, DD, 1, nt * 32, 128,
                  g_p_U + (size_t)ch * U2D, 2 * DD, nullptr, sm);
    } else if (blk < 192) {
        int b2 = blk - 128, nt = b2 & 15, ch = b2 >> 4, kb = ch * 128;
        gtile_mma(ci + kb, DD, 0, Wct + (size_t)(DD + kb) * DD, DD, 0, nt * 32, 128,
                  g_p_cq + (size_t)ch * BDSZ, DD, nullptr, sm);
    } else {
        int b2 = blk - 192, nt = b2 & 15, ch = b2 >> 4, kb = ch * 128;
        gtile_mma(mprev + kb, DD, 0, Wm + (size_t)kb * DD, DD, 0, nt * 32, 128,
                  g_p_mp + (size_t)ch * BDSZ, DD, nullptr, sm);
    }
}

// ---------------- kC: z partials (on-the-fly y) + g partials (128 blocks) ----------------
__global__ void __launch_bounds__(256)
kC_k(const float* ci, const float* __restrict__ Wkb,
     const float* __restrict__ Wg, const float* __restrict__ bm)
{
    __shared__ uint32_t sm[SMSZ];
    int blk = blockIdx.x;
    if (blk < 64) {
        int nt = blk & 15, ch = blk >> 4, kb = ch * 128;
        gtileZ_mma(Wkb, nt * 32, kb, g_p_z + (size_t)ch * BDSZ, bm, sm);
    } else {
        int b2 = blk - 64, nt = b2 & 15, ch = b2 >> 4, kb = ch * 128;
        gtile_mma(ci + kb, DD, 0, Wg + (size_t)kb * DD, DD, 0, nt * 32, 128,
                  g_p_g + (size_t)ch * BDSZ, DD, nullptr, sm);
    }
}

// ---------------- read attention (sums z partials + u2 from pU) ----------------
__global__ void __launch_bounds__(512)
read_attn_k()
{
    int b = blockIdx.x, tid = threadIdx.x;
    __shared__ float zs[DD];
    __shared__ float att[HW];
    __shared__ float red[16];
    {
        size_t j = (size_t)b * DD + tid;
        size_t j2 = (size_t)b * 2 * DD + DD + tid;
        float zv = g_p_z[j] + g_p_z[BDSZ + j] + g_p_z[2*BDSZ + j] + g_p_z[3*BDSZ + j]
                 + g_p_U[j2] + g_p_U[(size_t)U2D + j2]
                 + g_p_U[(size_t)2*U2D + j2] + g_p_U[(size_t)3*U2D + j2];
        zs[tid] = zv;
    }
    __syncthreads();
    int warp = tid >> 5, lane = tid & 31;
    const float* base = g_KBp + (size_t)b * HW * DD;
    for (int hw = warp; hw < HW; hw += 16) {
        const float4* row = (const float4*)(base + (size_t)hw * DD);
        const float4* z4 = (const float4*)zs;
        float acc = 0.f;
#pragma unroll
        for (int i = 0; i < 4; i++) {
            float4 kv = row[lane + i * 32];
            float4 zv = z4[lane + i * 32];
            acc += kv.x*zv.x + kv.y*zv.y + kv.z*zv.z + kv.w*zv.w;
        }
        for (int off = 16; off; off >>= 1) acc += __shfl_down_sync(~0u, acc, off);
        if (lane == 0) att[hw] = acc;
    }
    __syncthreads();
    float val = (tid < HW) ? att[tid] : -1e30f;
    float m = val;
    for (int off = 16; off; off >>= 1) m = fmaxf(m, __shfl_xor_sync(~0u, m, off));
    if (lane == 0) red[warp] = m;
    __syncthreads();
    if (warp == 0) {
        float mm = (lane < 16) ? red[lane] : -1e30f;
        for (int off = 8; off; off >>= 1) mm = fmaxf(mm, __shfl_xor_sync(~0u, mm, off));
        if (lane == 0) red[0] = mm;
    }
    __syncthreads();
    float mx = red[0];
    float e = (tid < HW) ? expf(val - mx) : 0.f;
    float s = e;
    for (int off = 16; off; off >>= 1) s += __shfl_xor_sync(~0u, s, off);
    __syncthreads();
    if (lane == 0) red[warp] = s;
    __syncthreads();
    if (warp == 0) {
        float ss = (lane < 16) ? red[lane] : 0.f;
        for (int off = 8; off; off >>= 1) ss += __shfl_xor_sync(~0u, ss, off);
        if (lane == 0) red[0] = ss;
    }
    __syncthreads();
    float inv = 1.f / red[0];
    if (tid < HW) att[tid] = e * inv;
    __syncthreads();
    const float* col = base + tid;
    float acc = 0.f;
#pragma unroll 4
    for (int hw = 0; hw < HW; hw++) acc += att[hw] * col[(size_t)hw * DD];
    g_mnew[(size_t)b * DD + tid] = acc;
}

// ---------------- kE: final partials [msa|mnew|m_prev] @ Wcomb (192 blocks) ----------------
__global__ void __launch_bounds__(256)
kE_k(const float* mprev)
{
    __shared__ uint32_t sm[SMSZ];
    int tile = blockIdx.x;
    int nt = tile & 15, ch = tile >> 4, kb = ch * 128;
    const float* A;
    if (kb < DD)            A = g_msa + kb;
    else if (kb < 2 * DD)   A = g_mnew + (kb - DD);
    else                    A = mprev + (kb - 2 * DD);
    gtile_mma(A, DD, 0, g_Wcomb + (size_t)kb * DD, DD, 0, nt * 32, 128,
              g_p_f + (size_t)ch * BDSZ, DD, nullptr, sm);
}

// ---------------- kF: reduce final + sigmoid gate ----------------
__global__ void gateF_k(const float* __restrict__ bg, const float* mprev,
                        float* mnext, float* out, int writeOut)
{
    int idx = blockIdx.x * 256 + threadIdx.x;
    int n = idx & 511;
    float m2 = g_bcomb[n];
#pragma unroll
    for (int c = 0; c < 12; c++) m2 += g_p_f[(size_t)c * BDSZ + idx];
    float gs = g_p_g[idx] + g_p_g[BDSZ + idx] + g_p_g[2*BDSZ + idx]
             + g_p_g[3*BDSZ + idx] + bg[n];
    float gg = 1.f / (1.f + expf(-gs));
    float r = gg * mprev[idx] + (1.f - gg) * m2;
    mnext[idx] = r;
    if (writeOut) out[idx] = r;
}

// ---------------- host ----------------
extern "C" void kernel_launch(void* const* d_in, const int* in_sizes, int n_in,
                              void* d_out, int out_size)
{
    const float* q   = (const float*)d_in[0];
    const float* cws = (const float*)d_in[1];
    const float* KB  = (const float*)d_in[2];
    const float* c0  = (const float*)d_in[3];
    const float* m0  = (const float*)d_in[4];
    const float* Wq  = (const float*)d_in[5];
    const float* bq  = (const float*)d_in[6];
    const float* Wct = (const float*)d_in[7];
    const float* bct = (const float*)d_in[8];
    const float* wca = (const float*)d_in[9];
    const float* Wm  = (const float*)d_in[11];
    const float* bm  = (const float*)d_in[12];
    const float* Wkb = (const float*)d_in[13];
    const float* Wrm = (const float*)d_in[15];
    const float* wra = (const float*)d_in[17];
    const float* Wwm = (const float*)d_in[19];
    const float* bwm = (const float*)d_in[20];
    const float* wwa = (const float*)d_in[21];
    const float* Wam = (const float*)d_in[23];
    const float* bam = (const float*)d_in[24];
    const float* Wg  = (const float*)d_in[25];
    const float* bg  = (const float*)d_in[26];

    float *KBp, *chist, *mhist, *qi, *cq0, *Wcomb, *p_set, *p_cq;
    cudaGetSymbolAddress((void**)&KBp,   g_KBp);
    cudaGetSymbolAddress((void**)&chist, g_chist);
    cudaGetSymbolAddress((void**)&mhist, g_mhist);
    cudaGetSymbolAddress((void**)&qi,    g_qi);
    cudaGetSymbolAddress((void**)&cq0,   g_cq0);
    cudaGetSymbolAddress((void**)&Wcomb, g_Wcomb);
    cudaGetSymbolAddress((void**)&p_set, g_p_set);
    cudaGetSymbolAddress((void**)&p_cq,  g_p_cq);

    // ---- setup ----
    cudaMemcpyAsync(chist, c0, BDSZ * sizeof(float), cudaMemcpyDeviceToDevice);
    cudaMemcpyAsync(mhist, m0, BDSZ * sizeof(float), cudaMemcpyDeviceToDevice);
    cudaMemcpyAsync(Wcomb, Wam, (size_t)DD * DD * sizeof(float), cudaMemcpyDeviceToDevice);

    transpose_kb_k<<<dim3((HW + 31) / 32, DD / 32, BB), dim3(32, 8)>>>(KB, KBp);
    bcomb_k<<<4, 128>>>(Wam, bwm, bam);

    GP p;
    // qi = q @ Wq + bq
    p = {q, DD, DD, Wq, 0, DD, p_set, BB, DD, 128};
    gpartial_k<<<dim3(16, 4), 256>>>(p);
    reduce0_k<<<BDSZ / 256, 256>>>(p_set, 4, BDSZ, DD, bq, qi);
    // cq0 = qi @ Wct_top + bct
    p = {qi, DD, DD, Wct, 0, DD, p_set, BB, DD, 128};
    gpartial_k<<<dim3(16, 4), 256>>>(p);
    reduce0_k<<<BDSZ / 256, 256>>>(p_set, 4, BDSZ, DD, bct, cq0);
    // Wcomb rows 512..1535 = Wwm @ Wam_bot
    p = {Wwm, DD, DD, Wam + (size_t)DD * DD, 0, DD, p_set, 2 * DD, DD, 128};
    gpartial_k<<<dim3(16 * 8, 4), 256>>>(p);
    reduce0_k<<<(2 * DD * DD) / 256, 256>>>(p_set, 4, 2 * DD * DD, DD, nullptr,
                                            Wcomb + (size_t)DD * DD);
    // cq partials for t=0: c0 @ Wct_bot
    p = {chist, DD, DD, Wct + (size_t)DD * DD, 0, DD, p_cq, BB, DD, 128};
    gpartial_k<<<dim3(16, 4), 256>>>(p);

    // ---- main recurrence: 6 launches per step ----
    for (int t = 0; t < TT; t++) {
        const float* mhist_t  = mhist + (size_t)t * BDSZ;
        float*       mhist_t1 = mhist + (size_t)(t + 1) * BDSZ;
        const float* ci_cur   = chist + (size_t)(t + 1) * BDSZ;

        attn1_k<<<BB, 128>>>(cws, wca, wra, wwa, t);
        kB_k<<<256, 256>>>(ci_cur, mhist_t, Wrm, Wct, Wm);
        kC_k<<<128, 256>>>(ci_cur, Wkb, Wg, bm);
        read_attn_k<<<BB, 512>>>();
        kE_k<<<192, 256>>>(mhist_t);
        gateF_k<<<BDSZ / 256, 256>>>(bg, mhist_t, mhist_t1, (float*)d_out,
                                     (t == TT - 1) ? 1 : 0);
    }
}